// round 16
// baseline (speedup 1.0000x reference)
#include <cuda_runtime.h>

// ChamferDistanceLoss via exact 1-D bucket-pruned NN (3 launches, NO smem
// staging). d2 >= dx^2: only points with |x_p - x_q| <= sqrt(best) can win.
// Refs bucketed by x, stored float4 {-2x,-2y,-2z,||p||^2}. Window kernel
// reads refs directly from global: the scan index j is warp-uniform, so
// every LDG.128 is a broadcast and the 64KB ref set stays L1/L2-hot.
// Seed best from the 128 x-nearest (by sorted index), then scan the exact
// warp-union x-window. Over-scan only confirms the min (exact).
// PAD rows: pn=3e38 as refs (never win); PAD queries substituted + masked.

#define PADV   10000.0f
#define NB     256
#define XMIN   (-6.0f)
#define INVW   (NB / 12.0f)
#define MAXB   8
#define MAXQ   4096

static __device__ float4 g_ref4[MAXB][2][MAXQ];  // bucketed: {-2x,-2y,-2z,pn}
static __device__ int    g_sidx[MAXB][2][MAXQ];  // bucketed slot -> original index
static __device__ int    g_boff[MAXB][2][NB + 1];
static __device__ float  g_min[2][MAXB][MAXQ];   // per-query min d2, original index

__device__ __forceinline__ int bucket_of(float x) {
    float t = (x - XMIN) * INVW;
    t = fminf(fmaxf(t, 0.0f), (float)(NB - 1));
    return (int)t;
}

// One block per (set, b), 1024 threads: histogram + warp prefix + scatter.
__global__ __launch_bounds__(1024) void bucket_kernel(const float* __restrict__ fg,
                                                      const float* __restrict__ prj,
                                                      float* out, int N, int M) {
    __shared__ int h[NB], off[NB + 1], cur[NB];
    int set = blockIdx.x, b = blockIdx.y;
    if (set == 0 && b == 0 && threadIdx.x == 0) out[0] = 0.0f;
    const float* pts = set ? prj : fg;
    int n = set ? M : N;

    for (int i = threadIdx.x; i < NB; i += blockDim.x) h[i] = 0;
    __syncthreads();
    for (int i = threadIdx.x; i < MAXQ; i += blockDim.x) {
        float x = (i < n) ? __ldg(&pts[((size_t)b * n + i) * 3]) : 3.0e38f;
        atomicAdd(&h[bucket_of(x)], 1);
    }
    __syncthreads();
    if (threadIdx.x < 32) {   // warp 0: exclusive prefix over 256 buckets
        int lane = threadIdx.x;
        int v[8], lsum = 0;
        #pragma unroll
        for (int k = 0; k < 8; k++) { v[k] = h[lane * 8 + k]; lsum += v[k]; }
        int excl = lsum;
        #pragma unroll
        for (int o = 1; o < 32; o <<= 1) {
            int t = __shfl_up_sync(0xFFFFFFFFu, excl, o);
            if (lane >= o) excl += t;
        }
        excl -= lsum;
        int run = excl;
        #pragma unroll
        for (int k = 0; k < 8; k++) { off[lane * 8 + k] = run; run += v[k]; }
        if (lane == 31) off[NB] = run;
    }
    __syncthreads();
    for (int i = threadIdx.x; i < NB; i += blockDim.x) cur[i] = off[i];
    for (int i = threadIdx.x; i <= NB; i += blockDim.x) g_boff[b][set][i] = off[i];
    __syncthreads();
    for (int i = threadIdx.x; i < MAXQ; i += blockDim.x) {
        float x, y, z, w;
        if (i < n) {
            const float* p = pts + ((size_t)b * n + i) * 3;
            x = __ldg(&p[0]); y = __ldg(&p[1]); z = __ldg(&p[2]);
            w = x * x + y * y + z * z;
        } else { x = 3.0e38f; y = 0.f; z = 0.f; w = 3.0e38f; }
        int pos = atomicAdd(&cur[bucket_of(x)], 1);
        g_ref4[b][set][pos] = make_float4(-2.f * x, -2.f * y, -2.f * z, w);
        g_sidx[b][set][pos] = (i < n) ? i : 0;
    }
}

// grid: (MAXQ/128, B, 2), 128 threads, no shared memory, no barriers.
// Warp = 32 x-adjacent bucketed queries; scan index is warp-uniform so all
// ref loads are broadcasts.
__global__ __launch_bounds__(128) void window_kernel(int N, int M) {
    int b = blockIdx.y, dir = blockIdx.z;
    int qset = dir ? 1 : 0;          // dir0: queries=fg(0), refs=prj(1)
    int rset = 1 - qset;
    int Nq = dir ? M : N;

    const float4* R   = &g_ref4[b][rset][0];
    const int*   boff = &g_boff[b][rset][0];

    int qi = blockIdx.x * blockDim.x + threadIdx.x;   // bucketed order
    bool inrange = qi < Nq;
    int qc = inrange ? qi : 0;
    float4 qv = g_ref4[b][qset][qc];
    float qx = -0.5f * qv.x, qy = -0.5f * qv.y, qz = -0.5f * qv.z, qn = qv.w;
    bool valid = inrange && (qx != PADV) && (qx < 1.0e37f);
    unsigned vmask = __ballot_sync(0xFFFFFFFFu, valid);
    if (vmask == 0) return;                 // warp-uniform; no barriers follow
    int src_lane = __ffs(vmask) - 1;
    {   // substitute a valid lane's query into invalid lanes (ALL lanes shfl)
        float tx = __shfl_sync(0xFFFFFFFFu, qx, src_lane);
        float ty = __shfl_sync(0xFFFFFFFFu, qy, src_lane);
        float tz = __shfl_sync(0xFFFFFFFFu, qz, src_lane);
        float tn = __shfl_sync(0xFFFFFFFFu, qn, src_lane);
        if (!valid) { qx = tx; qy = ty; qz = tz; qn = tn; }
    }

    int bq = bucket_of(qx);
    int bqlo = (int)__reduce_min_sync(0xFFFFFFFFu, (unsigned)bq);
    int bqhi = (int)__reduce_max_sync(0xFFFFFFFFu, (unsigned)bq);

    float best = 3.0e38f;   // running min of d' = pn - 2 q.p

    // ---- phase A: seed from 128 x-nearest by sorted index (warp-uniform) ----
    int c0, c1;
    {
        int center = (__ldg(&boff[bqlo]) + __ldg(&boff[bqhi + 1])) >> 1;
        c0 = max(center - 64, 0);
        c1 = min(c0 + 128, MAXQ);
        #pragma unroll 4
        for (int j = c0; j < c1; j++) {
            float4 p = __ldg(&R[j]);     // broadcast
            float d = fmaf(qx, p.x, p.w);
            d = fmaf(qy, p.y, d);
            d = fmaf(qz, p.z, d);
            best = fminf(best, d);
        }
    }

    // ---- phase B: exact window scan (skip the already-seeded gap) ----
    {
        float r = sqrtf(fmaxf(best + qn, 0.f) + 1e-4f) + 2e-3f;  // conservative
        int blo = bucket_of(qx - r), bhi = bucket_of(qx + r);
        blo = (int)__reduce_min_sync(0xFFFFFFFFu, (unsigned)blo);
        bhi = (int)__reduce_max_sync(0xFFFFFFFFu, (unsigned)bhi);
        int w0 = min(__ldg(&boff[blo]), c0);
        int w1 = max(__ldg(&boff[bhi + 1]), c1);
        // left of seed
        #pragma unroll 4
        for (int j = w0; j < c0; j++) {
            float4 p = __ldg(&R[j]);
            float d = fmaf(qx, p.x, p.w);
            d = fmaf(qy, p.y, d);
            d = fmaf(qz, p.z, d);
            best = fminf(best, d);
        }
        // right of seed
        #pragma unroll 4
        for (int j = c1; j < w1; j++) {
            float4 p = __ldg(&R[j]);
            float d = fmaf(qx, p.x, p.w);
            d = fmaf(qy, p.y, d);
            d = fmaf(qz, p.z, d);
            best = fminf(best, d);
        }
    }
    if (valid) g_min[dir][b][g_sidx[b][qset][qi]] = best + qn;
}

// grid: (B). Per-sample sums for both directions + atomicAdd into out.
__global__ __launch_bounds__(256) void reduce_final(const float* __restrict__ fg,
                                                    float* out, int N, int M, int B) {
    const int RT = 256;
    int b = blockIdx.x;
    float sx = 0.f, sy = 0.f, cv = 0.f;
    for (int i = threadIdx.x; i < N; i += RT) {
        if (fg[((size_t)b * N + i) * 3] != PADV) {
            sx += fmaxf(g_min[0][b][i], 0.f);
            cv += 1.f;
        }
    }
    for (int i = threadIdx.x; i < M; i += RT)
        sy += fmaxf(g_min[1][b][i], 0.f);

    #pragma unroll
    for (int o = 16; o > 0; o >>= 1) {
        sx += __shfl_xor_sync(0xFFFFFFFFu, sx, o);
        sy += __shfl_xor_sync(0xFFFFFFFFu, sy, o);
        cv += __shfl_xor_sync(0xFFFFFFFFu, cv, o);
    }
    __shared__ float ws[RT / 32][3];
    int wid = threadIdx.x / 32, lane = threadIdx.x % 32;
    if (lane == 0) { ws[wid][0] = sx; ws[wid][1] = sy; ws[wid][2] = cv; }
    __syncthreads();
    if (threadIdx.x == 0) {
        float tsx = 0.f, tsy = 0.f, tc = 0.f;
        for (int w = 0; w < RT / 32; w++) {
            tsx += ws[w][0]; tsy += ws[w][1]; tc += ws[w][2];
        }
        atomicAdd(out, (tsx / tc + tsy / (float)M) / (float)B);
    }
}

extern "C" void kernel_launch(void* const* d_in, const int* in_sizes, int n_in,
                              void* d_out, int out_size) {
    const float* fg  = (const float*)d_in[0];
    const float* prj = (const float*)d_in[1];
    int B = in_sizes[2];
    int N = in_sizes[0] / (3 * B);
    int M = in_sizes[1] / (3 * B);
    float* out = (float*)d_out;

    bucket_kernel<<<dim3(2, B), 1024>>>(fg, prj, out, N, M);
    int maxq = (N > M) ? N : M;
    int xblocks = (maxq + 127) / 128;               // 32 for 4096
    window_kernel<<<dim3(xblocks, B, 2), 128>>>(N, M);
    reduce_final<<<B, 256>>>(fg, out, N, M, B);
}